// round 13
// baseline (speedup 1.0000x reference)
#include <cuda_runtime.h>
#include <cstdint>

// ---------------- problem constants ----------------
#define B_    2
#define S_    4096
#define H_    16
#define NBLK  255
#define R_    512
#define ROPE_ 64
#define QKD_  192
#define VD_   128
#define KER_  32
#define STR_  16
#define TOPK_ 16
#define SCALE_ 0.07216878364870323f

#define KSPLIT 8

// ---------------- scratch (device globals; no cudaMalloc allowed) ----------
__device__ float g_scr_kv[KSPLIT * 512 * 512];
__device__ float g_scr_pe[KSPLIT * 512 * 64];
__device__ float g_cmp_kv[510 * 512];
__device__ float g_cmp_pe[510 * 64];
__device__ float g_Kf[(size_t)B_ * H_ * NBLK * QKD_];
__device__ float g_Vf[(size_t)B_ * H_ * NBLK * VD_];
__device__ float g_pagg[(size_t)B_ * S_ * 256];

// ---------------- helpers ----------------
__device__ __forceinline__ float tf32r(float x) {
    unsigned r; asm("cvt.rna.tf32.f32 %0, %1;" : "=r"(r) : "f"(x));
    return __uint_as_float(r);
}
__device__ __forceinline__ unsigned u32f(float x) { return __float_as_uint(x); }

__device__ __forceinline__ void mma_tf32(float c[4],
    unsigned a0, unsigned a1, unsigned a2, unsigned a3,
    unsigned b0, unsigned b1)
{
    asm volatile(
        "mma.sync.aligned.m16n8k8.row.col.f32.tf32.tf32.f32 "
        "{%0,%1,%2,%3},{%4,%5,%6,%7},{%8,%9},{%0,%1,%2,%3};"
        : "+f"(c[0]), "+f"(c[1]), "+f"(c[2]), "+f"(c[3])
        : "r"(a0), "r"(a1), "r"(a2), "r"(a3), "r"(b0), "r"(b1));
}

__device__ __forceinline__ void cp16(float* dst, const float* src, bool valid) {
    unsigned d = (unsigned)__cvta_generic_to_shared(dst);
    int sz = valid ? 16 : 0;
    asm volatile("cp.async.ca.shared.global [%0], [%1], 16, %2;\n"
                 :: "r"(d), "l"(src), "r"(sz));
}
#define CP_COMMIT() asm volatile("cp.async.commit_group;\n" ::: "memory")
#define CP_WAIT1()  asm volatile("cp.async.wait_group 1;\n" ::: "memory")
#define CP_WAIT0()  asm volatile("cp.async.wait_group 0;\n" ::: "memory")

// 2-op split, 3-term mma: h = rna(x), l = x-h passed RAW (hw truncates l to
// tf32; truncation error <= 2^-22 rel — same class as rounding l explicitly).
__device__ __forceinline__ void mma3(float acc[4],
    float q0, float q1, float q2, float q3, float b0v, float b1v)
{
    float h0 = tf32r(q0), h1 = tf32r(q1), h2 = tf32r(q2), h3 = tf32r(q3);
    float l0 = q0 - h0, l1 = q1 - h1, l2 = q2 - h2, l3 = q3 - h3;
    float bh0 = tf32r(b0v), bh1 = tf32r(b1v);
    float bl0 = b0v - bh0, bl1 = b1v - bh1;
    mma_tf32(acc, u32f(h0), u32f(h1), u32f(h2), u32f(h3), u32f(bh0), u32f(bh1));
    mma_tf32(acc, u32f(l0), u32f(l1), u32f(l2), u32f(l3), u32f(bh0), u32f(bh1));
    mma_tf32(acc, u32f(h0), u32f(h1), u32f(h2), u32f(h3), u32f(bl0), u32f(bl1));
}

// ---------------- zero p_agg (float4) ----------------
__global__ void zero_pagg_kernel() {
    size_t i = (size_t)blockIdx.x * blockDim.x + threadIdx.x;
    size_t n4 = (size_t)B_ * S_ * 256 / 4;
    if (i < n4) ((float4*)g_pagg)[i] = make_float4(0.f, 0.f, 0.f, 0.f);
}

// ---------------- gathered split-K GEMM (fp32 FFMA, R8-proven) ------------
__global__ void gather_gemm_kernel(const float* __restrict__ src,
                                   const float* __restrict__ W,
                                   int logF, int N, int KC, int mode)
{
    __shared__ float sA[16 * 65];
    __shared__ float sB[16 * 64];
    float* scratch = mode ? g_scr_pe : g_scr_kv;
    const int F = 1 << logF;
    const int m0 = blockIdx.x * 64, n0 = blockIdx.y * 64;
    const int k0 = blockIdx.z * KC;
    const int t = threadIdx.x;
    const int ty = t >> 4, tx = t & 15;

    float acc[4][4];
#pragma unroll
    for (int i = 0; i < 4; i++)
#pragma unroll
        for (int j = 0; j < 4; j++) acc[i][j] = 0.f;

    for (int ks = 0; ks < KC; ks += 16) {
#pragma unroll
        for (int i = 0; i < 4; i++) {
            int idx = t + i * 256;
            int mm = idx >> 4, kk = idx & 15;
            int m = m0 + mm;
            float v = 0.f;
            if (m < 510) {
                int bb = (m >= NBLK) ? 1 : 0;
                int nb = m - bb * NBLK;
                int k = k0 + ks + kk;
                int p = k >> logF, c = k & (F - 1);
                v = src[(((size_t)bb * S_ + nb * STR_ + p) << logF) + c];
            }
            sA[kk * 65 + mm] = v;
        }
#pragma unroll
        for (int i = 0; i < 4; i++) {
            int idx = t + i * 256;
            int kk = idx >> 6, nn = idx & 63;
            sB[kk * 64 + nn] = W[(size_t)(k0 + ks + kk) * N + n0 + nn];
        }
        __syncthreads();
#pragma unroll
        for (int kk = 0; kk < 16; kk++) {
            float a[4], bv[4];
#pragma unroll
            for (int i = 0; i < 4; i++) a[i] = sA[kk * 65 + ty + 16 * i];
#pragma unroll
            for (int j = 0; j < 4; j++) bv[j] = sB[kk * 64 + tx + 16 * j];
#pragma unroll
            for (int i = 0; i < 4; i++)
#pragma unroll
                for (int j = 0; j < 4; j++) acc[i][j] += a[i] * bv[j];
        }
        __syncthreads();
    }
#pragma unroll
    for (int i = 0; i < 4; i++)
#pragma unroll
        for (int j = 0; j < 4; j++)
            scratch[((size_t)blockIdx.z * 512 + m0 + ty + 16 * i) * N + n0 + tx + 16 * j] = acc[i][j];
}

// ---------------- split-K reduction ----------------
__global__ void reduce_kernel() {
    int i = blockIdx.x * blockDim.x + threadIdx.x;
    if (i < 510 * 512) {
        int m = i / 512, n = i % 512;
        float s = 0.f;
#pragma unroll
        for (int kc = 0; kc < KSPLIT; kc++) s += g_scr_kv[((size_t)kc * 512 + m) * 512 + n];
        g_cmp_kv[i] = s;
    } else if (i < 510 * 512 + 510 * 64) {
        int j = i - 510 * 512;
        int m = j / 64, e = j % 64;
        float s = 0.f;
#pragma unroll
        for (int kc = 0; kc < KSPLIT; kc++) s += g_scr_pe[((size_t)kc * 512 + m) * 64 + e];
        g_cmp_pe[j] = s;
    }
}

// ---------------- kvb GEMM (fp32 FFMA, R8-proven) + scatter ---------------
__global__ void kvb_gemm_kernel(const float* __restrict__ Wkb)
{
    __shared__ float sA[16 * 65];
    __shared__ float sB[16 * 64];
    const int m0 = blockIdx.x * 64, n0 = blockIdx.y * 64;
    const int t = threadIdx.x;
    const int ty = t >> 4, tx = t & 15;

    float acc[4][4];
#pragma unroll
    for (int i = 0; i < 4; i++)
#pragma unroll
        for (int j = 0; j < 4; j++) acc[i][j] = 0.f;

    for (int ks = 0; ks < 512; ks += 16) {
#pragma unroll
        for (int i = 0; i < 4; i++) {
            int idx = t + i * 256;
            int mm = idx >> 4, kk = idx & 15;
            int m = m0 + mm;
            sA[kk * 65 + mm] = (m < 510) ? g_cmp_kv[(size_t)m * 512 + ks + kk] : 0.f;
        }
#pragma unroll
        for (int i = 0; i < 4; i++) {
            int idx = t + i * 256;
            int kk = idx >> 6, nn = idx & 63;
            sB[kk * 64 + nn] = Wkb[(size_t)(ks + kk) * 4096 + n0 + nn];
        }
        __syncthreads();
#pragma unroll
        for (int kk = 0; kk < 16; kk++) {
            float a[4], bv[4];
#pragma unroll
            for (int i = 0; i < 4; i++) a[i] = sA[kk * 65 + ty + 16 * i];
#pragma unroll
            for (int j = 0; j < 4; j++) bv[j] = sB[kk * 64 + tx + 16 * j];
#pragma unroll
            for (int i = 0; i < 4; i++)
#pragma unroll
                for (int j = 0; j < 4; j++) acc[i][j] += a[i] * bv[j];
        }
        __syncthreads();
    }
#pragma unroll
    for (int i = 0; i < 4; i++) {
        int m = m0 + ty + 16 * i;
        if (m >= 510) continue;
        int bb = (m >= NBLK) ? 1 : 0;
        int nb = m - bb * NBLK;
#pragma unroll
        for (int j = 0; j < 4; j++) {
            int ng = n0 + tx + 16 * j;
            int h = ng >> 8, d = ng & 255;
            if (d < 128)
                g_Kf[((size_t)((bb * H_ + h) * NBLK + nb)) * QKD_ + d] = acc[i][j];
            else
                g_Vf[((size_t)((bb * H_ + h) * NBLK + nb)) * VD_ + (d - 128)] = acc[i][j];
        }
    }
}

// ---------------- broadcast rope into Kf[...,128:192] ----------------
__global__ void rope_fill_kernel() {
    int i = blockIdx.x * blockDim.x + threadIdx.x;
    const int tot = B_ * H_ * NBLK * ROPE_;
    if (i >= tot) return;
    int e = i & 63;
    int nb = (i >> 6) % NBLK;
    int h = (i / (64 * NBLK)) % H_;
    int b = i / (64 * NBLK * H_);
    g_Kf[((size_t)((b * H_ + h) * NBLK + nb)) * QKD_ + 128 + e] = g_cmp_pe[((size_t)(b * NBLK + nb)) * 64 + e];
}

// ---------------- attention ----------------
#define SP  260
#define QS  196
#define KS2 196
#define VS2 136
#define ATTN_SMEM_FLOATS (32 * SP + 19200)

__global__ void __launch_bounds__(256, 2)
attn_kernel(const float* __restrict__ q, float* __restrict__ out)
{
    extern __shared__ float sm[];
    float* sS   = sm;
    float* sBuf = sm + 32 * SP;
    float* sQ   = sBuf;
    float* sK0  = sBuf + 6400;
    float* sK1  = sBuf + 12672;
    float* sV0  = sBuf;
    float* sV1  = sBuf + 8704;

    // reversed: heaviest (largest s0) tiles scheduled first
    const int qt = (int)gridDim.x - 1 - (int)blockIdx.x;
    const int h = blockIdx.y, b = blockIdx.z;
    const int s0 = qt * 32;
    const int t = threadIdx.x;
    const int w = t >> 5, lane = t & 31;
    const int g = lane >> 2, tig = lane & 3;
    const int mrow = 16 * (w & 1);
    const int nloc8 = (w >> 1) * 8;

    const int nmax_tile = s0 >> 4;
    const int nkt = min(8, nmax_tile / 32 + 1);
    const int nvt = min(4, nmax_tile / 64 + 1);
    const int ncols = nvt * 64;

    const float* Kb = g_Kf + (size_t)(b * H_ + h) * NBLK * QKD_;
    const float* Vb = g_Vf + (size_t)(b * H_ + h) * NBLK * VD_;

    for (int i = t; i < 32 * 48; i += 256) {
        int r = i / 48, c = i % 48;
        cp16(sK0 + r * KS2 + c * 4, Kb + (size_t)r * QKD_ + c * 4, r < NBLK);
    }
    CP_COMMIT();

    const float* qb = q + ((size_t)(b * S_ + s0) * H_ + h) * QKD_;
    for (int i = t; i < 32 * 48; i += 256) {
        int r = i / 48, c = i % 48;
        float4 v = ((const float4*)(qb + (size_t)r * H_ * QKD_))[c];
        *(float4*)(sQ + r * QS + c * 4) = v;
    }

    for (int nt = 0; nt < nkt; nt++) {
        if (nt + 1 < nkt) {
            float* dst = ((nt + 1) & 1) ? sK1 : sK0;
            int n0 = (nt + 1) * 32;
            for (int i = t; i < 32 * 48; i += 256) {
                int r = i / 48, c = i % 48;
                int n = n0 + r;
                cp16(dst + r * KS2 + c * 4, Kb + (size_t)n * QKD_ + c * 4, n < NBLK);
            }
            CP_COMMIT();
            CP_WAIT1();
        } else {
            CP_WAIT0();
        }
        __syncthreads();

        const float* sK = (nt & 1) ? sK1 : sK0;
        float acc[4] = {0.f, 0.f, 0.f, 0.f};
#pragma unroll 2
        for (int k0 = 0; k0 < 192; k0 += 8) {
            float q0 = sQ[(mrow + g) * QS + k0 + tig];
            float q1 = sQ[(mrow + g + 8) * QS + k0 + tig];
            float q2 = sQ[(mrow + g) * QS + k0 + tig + 4];
            float q3 = sQ[(mrow + g + 8) * QS + k0 + tig + 4];
            float kv0 = sK[(nloc8 + g) * KS2 + k0 + tig];
            float kv1 = sK[(nloc8 + g) * KS2 + k0 + tig + 4];
            mma3(acc, q0, q1, q2, q3, kv0, kv1);
        }
        int col = nt * 32 + nloc8 + 2 * tig;
        *(float2*)(sS + (mrow + g) * SP + col)     = make_float2(acc[0], acc[1]);
        *(float2*)(sS + (mrow + g + 8) * SP + col) = make_float2(acc[2], acc[3]);
        __syncthreads();
    }

    for (int i = t; i < 64 * 32; i += 256) {
        int r = i / 32, c = i % 32;
        cp16(sV0 + r * VS2 + c * 4, Vb + (size_t)r * VD_ + c * 4, r < NBLK);
    }
    CP_COMMIT();

    const int tx = lane;
    for (int rr = 0; rr < 4; rr++) {
        int r = w * 4 + rr;
        int s = s0 + r;
        int nmax = (s >= 31) ? ((s - 31) >> 4) : -1;
        float m = -3.4e38f;
        for (int n = tx; n <= nmax; n += 32)
            m = fmaxf(m, sS[r * SP + n] * SCALE_);
#pragma unroll
        for (int o = 16; o; o >>= 1) m = fmaxf(m, __shfl_xor_sync(0xffffffffu, m, o));
        float L = 0.f;
        for (int n = tx; n < ncols; n += 32) {
            float e = 0.f;
            if (n <= nmax) e = __expf(sS[r * SP + n] * SCALE_ - m);
            sS[r * SP + n] = e;
            L += e;
        }
#pragma unroll
        for (int o = 16; o; o >>= 1) L += __shfl_xor_sync(0xffffffffu, L, o);
        if (nmax >= 0) {
            float inv = 1.f / L;
            for (int n = tx; n <= nmax; n += 32) {
                float p = sS[r * SP + n] * inv;                 // full fp32
                atomicMax((int*)&g_pagg[(size_t)(b * S_ + s) * 256 + n], __float_as_int(p));
                sS[r * SP + n] = tf32r(p);                      // pre-rounded for PV
            }
        }
    }
    __syncthreads();

    const int nquad = w >> 1;
    float oa[4][4];
#pragma unroll
    for (int j = 0; j < 4; j++)
#pragma unroll
        for (int e = 0; e < 4; e++) oa[j][e] = 0.f;

    for (int vt = 0; vt < nvt; vt++) {
        if (vt + 1 < nvt) {
            float* dst = ((vt + 1) & 1) ? sV1 : sV0;
            int n0 = (vt + 1) * 64;
            for (int i = t; i < 64 * 32; i += 256) {
                int r = i / 32, c = i % 32;
                int n = n0 + r;
                cp16(dst + r * VS2 + c * 4, Vb + (size_t)n * VD_ + c * 4, n < NBLK);
            }
            CP_COMMIT();
            CP_WAIT1();
        } else {
            CP_WAIT0();
        }
        __syncthreads();

        const float* sV = (vt & 1) ? sV1 : sV0;
#pragma unroll 2
        for (int ks = 0; ks < 64; ks += 8) {
            int k0 = vt * 64 + ks;
            unsigned a0 = u32f(sS[(mrow + g) * SP + k0 + tig]);      // pre-rounded
            unsigned a1 = u32f(sS[(mrow + g + 8) * SP + k0 + tig]);
            unsigned a2 = u32f(sS[(mrow + g) * SP + k0 + tig + 4]);
            unsigned a3 = u32f(sS[(mrow + g + 8) * SP + k0 + tig + 4]);
#pragma unroll
            for (int j = 0; j < 4; j++) {
                const float* vb = sV + (ks + tig) * VS2 + nquad * 32 + j * 8 + g;
                unsigned b0 = u32f(tf32r(vb[0]));
                unsigned b1 = u32f(tf32r(vb[4 * VS2]));
                mma_tf32(oa[j], a0, a1, a2, a3, b0, b1);
            }
        }
        __syncthreads();
    }

#pragma unroll
    for (int j = 0; j < 4; j++) {
        int col = nquad * 32 + j * 8 + 2 * tig;
        {
            int s = s0 + mrow + g;
            float* orow = out + (size_t)(b * S_ + s) * (H_ * VD_) + h * VD_ + col;
            *(float2*)orow = make_float2(oa[j][0], oa[j][1]);
        }
        {
            int s = s0 + mrow + g + 8;
            float* orow = out + (size_t)(b * S_ + s) * (H_ * VD_) + h * VD_ + col;
            *(float2*)orow = make_float2(oa[j][2], oa[j][3]);
        }
    }
}

// ---------------- top-k selection ----------------
__global__ void topk_kernel(float* __restrict__ out)
{
    int idx = blockIdx.x * blockDim.x + threadIdx.x;
    if (idx >= B_ * S_) return;
    int s = idx & (S_ - 1);
    int jt = s >> 6;
    const float* pa = g_pagg + (size_t)idx * 256;

    float sc[64];
#pragma unroll 1
    for (int j = 0; j < 64; j++) {
        if (j > jt)                { sc[j] = -1e9f; continue; }
        if (j == 0 || j >= jt - 1) { sc[j] =  1e9f; continue; }
        int nlo = 4 * j - 1;
        int nhi = min(NBLK - 1, 4 * j + 3);
        float sum = 0.f;
        for (int n = nlo; n <= nhi; n++) sum += pa[n];
        sc[j] = sum;
    }
    float* o = out + (size_t)B_ * S_ * (H_ * VD_) + (size_t)idx * TOPK_;
#pragma unroll 1
    for (int k = 0; k < TOPK_; k++) {
        float best = -3.4e38f; int bi = 0;
        for (int j = 0; j < 64; j++)
            if (sc[j] > best) { best = sc[j]; bi = j; }
        o[k] = (best <= -5e8f) ? -1.f : (float)bi;
        sc[bi] = -3.4e38f;
    }
}

// ---------------- launch ----------------
extern "C" void kernel_launch(void* const* d_in, const int* in_sizes, int n_in,
                              void* d_out, int out_size)
{
    const float* q       = (const float*)d_in[0];
    const float* kv_lora = (const float*)d_in[1];
    const float* k_pe    = (const float*)d_in[2];
    const float* Wck     = (const float*)d_in[3];
    const float* Wcp     = (const float*)d_in[4];
    const float* Wkb     = (const float*)d_in[5];
    float* out = (float*)d_out;

    cudaFuncSetAttribute(attn_kernel, cudaFuncAttributeMaxDynamicSharedMemorySize,
                         ATTN_SMEM_FLOATS * (int)sizeof(float));

    // 0) cmp_kv split-K (FFMA): M=512(510), N=512, K=16384
    gather_gemm_kernel<<<dim3(8, 8, KSPLIT), 256>>>(kv_lora, Wck, 9, 512, 2048, 0);
    // 1) cmp_pe split-K (FFMA): M=512(510), N=64, K=2048
    gather_gemm_kernel<<<dim3(8, 1, KSPLIT), 256>>>(k_pe, Wcp, 6, 64, 256, 1);
    // 2) reduce partials
    {
        int tot = 510 * 512 + 510 * 64;
        reduce_kernel<<<(tot + 255) / 256, 256>>>();
    }
    // 3) kvb GEMM + scatter  (ncu capture slot -> profiles this next round)
    kvb_gemm_kernel<<<dim3(8, 64), 256>>>(Wkb);
    // 4) zero p_agg
    {
        size_t n4 = (size_t)B_ * S_ * 256 / 4;
        zero_pagg_kernel<<<(unsigned)((n4 + 255) / 256), 256>>>();
    }
    // 5) rope broadcast into Kf
    {
        int tot = B_ * H_ * NBLK * ROPE_;
        rope_fill_kernel<<<(tot + 255) / 256, 256>>>();
    }
    // 6) attention (+ probs max into p_agg)
    attn_kernel<<<dim3(S_ / 32, H_, B_), 256, ATTN_SMEM_FLOATS * (int)sizeof(float)>>>(q, out);
    // 7) top-k indices
    topk_kernel<<<(B_ * S_ + 255) / 256, 256>>>(out);
}

// round 14
// speedup vs baseline: 1.7238x; 1.7238x over previous
#include <cuda_runtime.h>
#include <cstdint>

// ---------------- problem constants ----------------
#define B_    2
#define S_    4096
#define H_    16
#define NBLK  255
#define R_    512
#define ROPE_ 64
#define QKD_  192
#define VD_   128
#define KER_  32
#define STR_  16
#define TOPK_ 16
#define SCALE_ 0.07216878364870323f

#define KSPLIT 8

// ---------------- scratch (device globals; no cudaMalloc allowed) ----------
__device__ float g_scr_kv[KSPLIT * 512 * 512];
__device__ float g_scr_pe[KSPLIT * 512 * 64];
__device__ float g_cmp_kv[510 * 512];
__device__ float g_cmp_pe[510 * 64];
__device__ float g_Kf[(size_t)B_ * H_ * NBLK * QKD_];
__device__ float g_Vf[(size_t)B_ * H_ * NBLK * VD_];
__device__ float g_pagg[(size_t)B_ * S_ * 256];

// ---------------- helpers ----------------
__device__ __forceinline__ float tf32r(float x) {
    unsigned r; asm("cvt.rna.tf32.f32 %0, %1;" : "=r"(r) : "f"(x));
    return __uint_as_float(r);
}
__device__ __forceinline__ unsigned u32f(float x) { return __float_as_uint(x); }

__device__ __forceinline__ void mma_tf32(float c[4],
    unsigned a0, unsigned a1, unsigned a2, unsigned a3,
    unsigned b0, unsigned b1)
{
    asm volatile(
        "mma.sync.aligned.m16n8k8.row.col.f32.tf32.tf32.f32 "
        "{%0,%1,%2,%3},{%4,%5,%6,%7},{%8,%9},{%0,%1,%2,%3};"
        : "+f"(c[0]), "+f"(c[1]), "+f"(c[2]), "+f"(c[3])
        : "r"(a0), "r"(a1), "r"(a2), "r"(a3), "r"(b0), "r"(b1));
}

__device__ __forceinline__ void cp16(float* dst, const float* src, bool valid) {
    unsigned d = (unsigned)__cvta_generic_to_shared(dst);
    int sz = valid ? 16 : 0;
    asm volatile("cp.async.ca.shared.global [%0], [%1], 16, %2;\n"
                 :: "r"(d), "l"(src), "r"(sz));
}
#define CP_COMMIT() asm volatile("cp.async.commit_group;\n" ::: "memory")
#define CP_WAIT1()  asm volatile("cp.async.wait_group 1;\n" ::: "memory")
#define CP_WAIT0()  asm volatile("cp.async.wait_group 0;\n" ::: "memory")

// 3-term split with explicit tf32 rounding of residuals (R6-R11 validated)
__device__ __forceinline__ void mma3(float acc[4],
    float q0, float q1, float q2, float q3, float b0v, float b1v)
{
    float h0 = tf32r(q0), h1 = tf32r(q1), h2 = tf32r(q2), h3 = tf32r(q3);
    float l0 = tf32r(q0 - h0), l1 = tf32r(q1 - h1);
    float l2 = tf32r(q2 - h2), l3 = tf32r(q3 - h3);
    float bh0 = tf32r(b0v), bh1 = tf32r(b1v);
    float bl0 = tf32r(b0v - bh0), bl1 = tf32r(b1v - bh1);
    mma_tf32(acc, u32f(h0), u32f(h1), u32f(h2), u32f(h3), u32f(bh0), u32f(bh1));
    mma_tf32(acc, u32f(l0), u32f(l1), u32f(l2), u32f(l3), u32f(bh0), u32f(bh1));
    mma_tf32(acc, u32f(h0), u32f(h1), u32f(h2), u32f(h3), u32f(bl0), u32f(bl1));
}

// ---------------- zero p_agg (float4, half per launch) ----------------
__global__ void zero_pagg_kernel(int half) {
    size_t n4 = (size_t)B_ * S_ * 256 / 4;
    size_t i = (size_t)half * (n4 / 2) + (size_t)blockIdx.x * blockDim.x + threadIdx.x;
    size_t end = (size_t)(half + 1) * (n4 / 2);
    if (i < end) ((float4*)g_pagg)[i] = make_float4(0.f, 0.f, 0.f, 0.f);
}

// ---------------- gathered split-K GEMM (fp32 FFMA, vectorized) -----------
// bit-identical k-accumulation order to R8/R11; only thread mapping changed.
__global__ void gather_gemm_kernel(const float* __restrict__ src,
                                   const float* __restrict__ W,
                                   int logF, int N, int KC, int mode)
{
    __shared__ float sA[16 * 68];
    __shared__ float sB[16 * 64];
    float* scratch = mode ? g_scr_pe : g_scr_kv;
    const int F = 1 << logF;
    const int m0 = blockIdx.x * 64, n0 = blockIdx.y * 64;
    const int k0 = blockIdx.z * KC;
    const int t = threadIdx.x;
    const int ty = t >> 4, tx = t & 15;
    const int lmm = t >> 2, lkk0 = (t & 3) * 4;     // A loader mapping
    const int lr = t >> 4, lc4 = (t & 15) * 4;      // B loader mapping

    float acc[4][4];
#pragma unroll
    for (int i = 0; i < 4; i++)
#pragma unroll
        for (int j = 0; j < 4; j++) acc[i][j] = 0.f;

    for (int ks = 0; ks < KC; ks += 16) {
        // A tile: one LDG.128 per thread (gathered); 4 consecutive k stay in
        // one source row (k-tile 16-aligned, F in {512,64}).
        {
            int m = m0 + lmm;
            float4 v = make_float4(0.f, 0.f, 0.f, 0.f);
            if (m < 510) {
                int bb = (m >= NBLK) ? 1 : 0;
                int nb = m - bb * NBLK;
                int k = k0 + ks + lkk0;
                int p = k >> logF, c = k & (F - 1);
                v = *(const float4*)&src[(((size_t)bb * S_ + nb * STR_ + p) << logF) + c];
            }
            sA[(lkk0 + 0) * 68 + lmm] = v.x;
            sA[(lkk0 + 1) * 68 + lmm] = v.y;
            sA[(lkk0 + 2) * 68 + lmm] = v.z;
            sA[(lkk0 + 3) * 68 + lmm] = v.w;
        }
        // B tile: LDG.128 + STS.128
        *(float4*)&sB[lr * 64 + lc4] =
            *(const float4*)&W[(size_t)(k0 + ks + lr) * N + n0 + lc4];
        __syncthreads();
#pragma unroll
        for (int kk = 0; kk < 16; kk++) {
            float4 av = *(const float4*)&sA[kk * 68 + ty * 4];
            float4 bv = *(const float4*)&sB[kk * 64 + tx * 4];
            acc[0][0] += av.x * bv.x; acc[0][1] += av.x * bv.y; acc[0][2] += av.x * bv.z; acc[0][3] += av.x * bv.w;
            acc[1][0] += av.y * bv.x; acc[1][1] += av.y * bv.y; acc[1][2] += av.y * bv.z; acc[1][3] += av.y * bv.w;
            acc[2][0] += av.z * bv.x; acc[2][1] += av.z * bv.y; acc[2][2] += av.z * bv.z; acc[2][3] += av.z * bv.w;
            acc[3][0] += av.w * bv.x; acc[3][1] += av.w * bv.y; acc[3][2] += av.w * bv.z; acc[3][3] += av.w * bv.w;
        }
        __syncthreads();
    }
#pragma unroll
    for (int i = 0; i < 4; i++) {
        size_t row = (size_t)blockIdx.z * 512 + m0 + ty * 4 + i;
        *(float4*)&scratch[row * N + n0 + tx * 4] =
            make_float4(acc[i][0], acc[i][1], acc[i][2], acc[i][3]);
    }
}

// ---------------- split-K reduction ----------------
__global__ void reduce_kernel() {
    int i = blockIdx.x * blockDim.x + threadIdx.x;
    if (i < 510 * 512) {
        int m = i / 512, n = i % 512;
        float s = 0.f;
#pragma unroll
        for (int kc = 0; kc < KSPLIT; kc++) s += g_scr_kv[((size_t)kc * 512 + m) * 512 + n];
        g_cmp_kv[i] = s;
    } else if (i < 510 * 512 + 510 * 64) {
        int j = i - 510 * 512;
        int m = j / 64, e = j % 64;
        float s = 0.f;
#pragma unroll
        for (int kc = 0; kc < KSPLIT; kc++) s += g_scr_pe[((size_t)kc * 512 + m) * 64 + e];
        g_cmp_pe[j] = s;
    }
}

// ---------------- kvb GEMM (fp32 FFMA, vectorized) + scatter --------------
__global__ void kvb_gemm_kernel(const float* __restrict__ Wkb)
{
    __shared__ float sA[16 * 68];
    __shared__ float sB[16 * 64];
    const int m0 = blockIdx.x * 64, n0 = blockIdx.y * 64;
    const int t = threadIdx.x;
    const int ty = t >> 4, tx = t & 15;
    const int lmm = t >> 2, lkk0 = (t & 3) * 4;
    const int lr = t >> 4, lc4 = (t & 15) * 4;

    float acc[4][4];
#pragma unroll
    for (int i = 0; i < 4; i++)
#pragma unroll
        for (int j = 0; j < 4; j++) acc[i][j] = 0.f;

    for (int ks = 0; ks < 512; ks += 16) {
        {
            int m = m0 + lmm;
            float4 v = make_float4(0.f, 0.f, 0.f, 0.f);
            if (m < 510)
                v = *(const float4*)&g_cmp_kv[(size_t)m * 512 + ks + lkk0];
            sA[(lkk0 + 0) * 68 + lmm] = v.x;
            sA[(lkk0 + 1) * 68 + lmm] = v.y;
            sA[(lkk0 + 2) * 68 + lmm] = v.z;
            sA[(lkk0 + 3) * 68 + lmm] = v.w;
        }
        *(float4*)&sB[lr * 64 + lc4] =
            *(const float4*)&Wkb[(size_t)(ks + lr) * 4096 + n0 + lc4];
        __syncthreads();
#pragma unroll
        for (int kk = 0; kk < 16; kk++) {
            float4 av = *(const float4*)&sA[kk * 68 + ty * 4];
            float4 bv = *(const float4*)&sB[kk * 64 + tx * 4];
            acc[0][0] += av.x * bv.x; acc[0][1] += av.x * bv.y; acc[0][2] += av.x * bv.z; acc[0][3] += av.x * bv.w;
            acc[1][0] += av.y * bv.x; acc[1][1] += av.y * bv.y; acc[1][2] += av.y * bv.z; acc[1][3] += av.y * bv.w;
            acc[2][0] += av.z * bv.x; acc[2][1] += av.z * bv.y; acc[2][2] += av.z * bv.z; acc[2][3] += av.z * bv.w;
            acc[3][0] += av.w * bv.x; acc[3][1] += av.w * bv.y; acc[3][2] += av.w * bv.z; acc[3][3] += av.w * bv.w;
        }
        __syncthreads();
    }
    // scatter: a 4-aligned col quad never straddles d=128 (K/V split)
#pragma unroll
    for (int i = 0; i < 4; i++) {
        int m = m0 + ty * 4 + i;
        if (m >= 510) continue;
        int bb = (m >= NBLK) ? 1 : 0;
        int nb = m - bb * NBLK;
        int col = n0 + tx * 4;
        int hh = col >> 8, d = col & 255;
        float4 v = make_float4(acc[i][0], acc[i][1], acc[i][2], acc[i][3]);
        if (d < 128)
            *(float4*)&g_Kf[((size_t)((bb * H_ + hh) * NBLK + nb)) * QKD_ + d] = v;
        else
            *(float4*)&g_Vf[((size_t)((bb * H_ + hh) * NBLK + nb)) * VD_ + (d - 128)] = v;
    }
}

// ---------------- broadcast rope into Kf[...,128:192] ----------------
__global__ void rope_fill_kernel() {
    int i = blockIdx.x * blockDim.x + threadIdx.x;
    const int tot = B_ * H_ * NBLK * ROPE_;
    if (i >= tot) return;
    int e = i & 63;
    int nb = (i >> 6) % NBLK;
    int h = (i / (64 * NBLK)) % H_;
    int b = i / (64 * NBLK * H_);
    g_Kf[((size_t)((b * H_ + h) * NBLK + nb)) * QKD_ + 128 + e] = g_cmp_pe[((size_t)(b * NBLK + nb)) * 64 + e];
}

// ---------------- attention (exact R11 version) ----------------
#define SP  260
#define QS  196
#define KS2 196
#define VS2 136
#define ATTN_SMEM_FLOATS (32 * SP + 19200)

__global__ void __launch_bounds__(256, 2)
attn_kernel(const float* __restrict__ q, float* __restrict__ out)
{
    extern __shared__ float sm[];
    float* sS   = sm;
    float* sBuf = sm + 32 * SP;
    float* sQ   = sBuf;
    float* sK0  = sBuf + 6400;
    float* sK1  = sBuf + 12672;
    float* sV0  = sBuf;
    float* sV1  = sBuf + 8704;

    const int qt = (int)gridDim.x - 1 - (int)blockIdx.x;
    const int h = blockIdx.y, b = blockIdx.z;
    const int s0 = qt * 32;
    const int t = threadIdx.x;
    const int w = t >> 5, lane = t & 31;
    const int g = lane >> 2, tig = lane & 3;
    const int mrow = 16 * (w & 1);
    const int nloc8 = (w >> 1) * 8;

    const int nmax_tile = s0 >> 4;
    const int nkt = min(8, nmax_tile / 32 + 1);
    const int nvt = min(4, nmax_tile / 64 + 1);
    const int ncols = nvt * 64;

    const float* Kb = g_Kf + (size_t)(b * H_ + h) * NBLK * QKD_;
    const float* Vb = g_Vf + (size_t)(b * H_ + h) * NBLK * VD_;

    for (int i = t; i < 32 * 48; i += 256) {
        int r = i / 48, c = i % 48;
        cp16(sK0 + r * KS2 + c * 4, Kb + (size_t)r * QKD_ + c * 4, r < NBLK);
    }
    CP_COMMIT();

    const float* qb = q + ((size_t)(b * S_ + s0) * H_ + h) * QKD_;
    for (int i = t; i < 32 * 48; i += 256) {
        int r = i / 48, c = i % 48;
        float4 v = ((const float4*)(qb + (size_t)r * H_ * QKD_))[c];
        *(float4*)(sQ + r * QS + c * 4) = v;
    }

    for (int nt = 0; nt < nkt; nt++) {
        if (nt + 1 < nkt) {
            float* dst = ((nt + 1) & 1) ? sK1 : sK0;
            int n0 = (nt + 1) * 32;
            for (int i = t; i < 32 * 48; i += 256) {
                int r = i / 48, c = i % 48;
                int n = n0 + r;
                cp16(dst + r * KS2 + c * 4, Kb + (size_t)n * QKD_ + c * 4, n < NBLK);
            }
            CP_COMMIT();
            CP_WAIT1();
        } else {
            CP_WAIT0();
        }
        __syncthreads();

        const float* sK = (nt & 1) ? sK1 : sK0;
        float acc[4] = {0.f, 0.f, 0.f, 0.f};
#pragma unroll 2
        for (int k0 = 0; k0 < 192; k0 += 8) {
            float q0 = sQ[(mrow + g) * QS + k0 + tig];
            float q1 = sQ[(mrow + g + 8) * QS + k0 + tig];
            float q2 = sQ[(mrow + g) * QS + k0 + tig + 4];
            float q3 = sQ[(mrow + g + 8) * QS + k0 + tig + 4];
            float kv0 = sK[(nloc8 + g) * KS2 + k0 + tig];
            float kv1 = sK[(nloc8 + g) * KS2 + k0 + tig + 4];
            mma3(acc, q0, q1, q2, q3, kv0, kv1);
        }
        int col = nt * 32 + nloc8 + 2 * tig;
        *(float2*)(sS + (mrow + g) * SP + col)     = make_float2(acc[0], acc[1]);
        *(float2*)(sS + (mrow + g + 8) * SP + col) = make_float2(acc[2], acc[3]);
        __syncthreads();
    }

    for (int i = t; i < 64 * 32; i += 256) {
        int r = i / 32, c = i % 32;
        cp16(sV0 + r * VS2 + c * 4, Vb + (size_t)r * VD_ + c * 4, r < NBLK);
    }
    CP_COMMIT();

    const int tx = lane;
    for (int rr = 0; rr < 4; rr++) {
        int r = w * 4 + rr;
        int s = s0 + r;
        int nmax = (s >= 31) ? ((s - 31) >> 4) : -1;
        float m = -3.4e38f;
        for (int n = tx; n <= nmax; n += 32)
            m = fmaxf(m, sS[r * SP + n] * SCALE_);
#pragma unroll
        for (int o = 16; o; o >>= 1) m = fmaxf(m, __shfl_xor_sync(0xffffffffu, m, o));
        float L = 0.f;
        for (int n = tx; n < ncols; n += 32) {
            float e = 0.f;
            if (n <= nmax) e = __expf(sS[r * SP + n] * SCALE_ - m);
            sS[r * SP + n] = e;
            L += e;
        }
#pragma unroll
        for (int o = 16; o; o >>= 1) L += __shfl_xor_sync(0xffffffffu, L, o);
        if (nmax >= 0) {
            float inv = 1.f / L;
            for (int n = tx; n <= nmax; n += 32) {
                float p = sS[r * SP + n] * inv;
                sS[r * SP + n] = p;
                atomicMax((int*)&g_pagg[(size_t)(b * S_ + s) * 256 + n], __float_as_int(p));
            }
        }
    }
    __syncthreads();

    const int nquad = w >> 1;
    float oa[4][4];
#pragma unroll
    for (int j = 0; j < 4; j++)
#pragma unroll
        for (int e = 0; e < 4; e++) oa[j][e] = 0.f;

    for (int vt = 0; vt < nvt; vt++) {
        if (vt + 1 < nvt) {
            float* dst = ((vt + 1) & 1) ? sV1 : sV0;
            int n0 = (vt + 1) * 64;
            for (int i = t; i < 64 * 32; i += 256) {
                int r = i / 32, c = i % 32;
                int n = n0 + r;
                cp16(dst + r * VS2 + c * 4, Vb + (size_t)n * VD_ + c * 4, n < NBLK);
            }
            CP_COMMIT();
            CP_WAIT1();
        } else {
            CP_WAIT0();
        }
        __syncthreads();

        const float* sV = (vt & 1) ? sV1 : sV0;
#pragma unroll 2
        for (int ks = 0; ks < 64; ks += 8) {
            int k0 = vt * 64 + ks;
            unsigned a0 = u32f(tf32r(sS[(mrow + g) * SP + k0 + tig]));
            unsigned a1 = u32f(tf32r(sS[(mrow + g + 8) * SP + k0 + tig]));
            unsigned a2 = u32f(tf32r(sS[(mrow + g) * SP + k0 + tig + 4]));
            unsigned a3 = u32f(tf32r(sS[(mrow + g + 8) * SP + k0 + tig + 4]));
#pragma unroll
            for (int j = 0; j < 4; j++) {
                const float* vb = sV + (ks + tig) * VS2 + nquad * 32 + j * 8 + g;
                unsigned b0 = u32f(tf32r(vb[0]));
                unsigned b1 = u32f(tf32r(vb[4 * VS2]));
                mma_tf32(oa[j], a0, a1, a2, a3, b0, b1);
            }
        }
        __syncthreads();
    }

#pragma unroll
    for (int j = 0; j < 4; j++) {
        int col = nquad * 32 + j * 8 + 2 * tig;
        {
            int s = s0 + mrow + g;
            float* orow = out + (size_t)(b * S_ + s) * (H_ * VD_) + h * VD_ + col;
            *(float2*)orow = make_float2(oa[j][0], oa[j][1]);
        }
        {
            int s = s0 + mrow + g + 8;
            float* orow = out + (size_t)(b * S_ + s) * (H_ * VD_) + h * VD_ + col;
            *(float2*)orow = make_float2(oa[j][2], oa[j][3]);
        }
    }
}

// ---------------- top-k selection ----------------
__global__ void topk_kernel(float* __restrict__ out)
{
    int idx = blockIdx.x * blockDim.x + threadIdx.x;
    if (idx >= B_ * S_) return;
    int s = idx & (S_ - 1);
    int jt = s >> 6;
    const float* pa = g_pagg + (size_t)idx * 256;

    float sc[64];
#pragma unroll 1
    for (int j = 0; j < 64; j++) {
        if (j > jt)                { sc[j] = -1e9f; continue; }
        if (j == 0 || j >= jt - 1) { sc[j] =  1e9f; continue; }
        int nlo = 4 * j - 1;
        int nhi = min(NBLK - 1, 4 * j + 3);
        float sum = 0.f;
        for (int n = nlo; n <= nhi; n++) sum += pa[n];
        sc[j] = sum;
    }
    float* o = out + (size_t)B_ * S_ * (H_ * VD_) + (size_t)idx * TOPK_;
#pragma unroll 1
    for (int k = 0; k < TOPK_; k++) {
        float best = -3.4e38f; int bi = 0;
        for (int j = 0; j < 64; j++)
            if (sc[j] > best) { best = sc[j]; bi = j; }
        o[k] = (best <= -5e8f) ? -1.f : (float)bi;
        sc[bi] = -3.4e38f;
    }
}

// ---------------- launch ----------------
extern "C" void kernel_launch(void* const* d_in, const int* in_sizes, int n_in,
                              void* d_out, int out_size)
{
    const float* q       = (const float*)d_in[0];
    const float* kv_lora = (const float*)d_in[1];
    const float* k_pe    = (const float*)d_in[2];
    const float* Wck     = (const float*)d_in[3];
    const float* Wcp     = (const float*)d_in[4];
    const float* Wkb     = (const float*)d_in[5];
    float* out = (float*)d_out;

    cudaFuncSetAttribute(attn_kernel, cudaFuncAttributeMaxDynamicSharedMemorySize,
                         ATTN_SMEM_FLOATS * (int)sizeof(float));

    const unsigned zblk = (unsigned)(((size_t)B_ * S_ * 256 / 8) + 255) / 256;

    // 0) zero p_agg (first half)
    zero_pagg_kernel<<<zblk, 256>>>(0);
    // 1) cmp_pe split-K: M=512(510), N=64, K=2048
    gather_gemm_kernel<<<dim3(8, 1, KSPLIT), 256>>>(k_pe, Wcp, 6, 64, 256, 1);
    // 2) zero p_agg (second half)
    zero_pagg_kernel<<<zblk, 256>>>(1);
    // 3) cmp_kv split-K  (ncu capture slot -> profiles the big gather GEMM)
    gather_gemm_kernel<<<dim3(8, 8, KSPLIT), 256>>>(kv_lora, Wck, 9, 512, 2048, 0);
    // 4) reduce partials
    {
        int tot = 510 * 512 + 510 * 64;
        reduce_kernel<<<(tot + 255) / 256, 256>>>();
    }
    // 5) kvb GEMM + scatter to Kf/Vf
    kvb_gemm_kernel<<<dim3(8, 64), 256>>>(Wkb);
    // 6) rope broadcast into Kf
    {
        int tot = B_ * H_ * NBLK * ROPE_;
        rope_fill_kernel<<<(tot + 255) / 256, 256>>>();
    }
    // 7) attention (+ probs max into p_agg)
    attn_kernel<<<dim3(S_ / 32, H_, B_), 256, ATTN_SMEM_FLOATS * (int)sizeof(float)>>>(q, out);
    // 8) top-k indices
    topk_kernel<<<(B_ * S_ + 255) / 256, 256>>>(out);
}

// round 15
// speedup vs baseline: 1.9180x; 1.1127x over previous
#include <cuda_runtime.h>
#include <cstdint>

// ---------------- problem constants ----------------
#define B_    2
#define S_    4096
#define H_    16
#define NBLK  255
#define R_    512
#define ROPE_ 64
#define QKD_  192
#define VD_   128
#define KER_  32
#define STR_  16
#define TOPK_ 16
#define SCALE_ 0.07216878364870323f

#define KSPLIT 8

// ---------------- scratch (device globals; no cudaMalloc allowed) ----------
__device__ float g_scr_kv[KSPLIT * 512 * 512];
__device__ float g_scr_pe[KSPLIT * 512 * 64];
__device__ float g_cmp_kv[510 * 512];
__device__ float g_cmp_pe[510 * 64];
__device__ float g_Kf[(size_t)B_ * H_ * NBLK * QKD_];
__device__ float g_Vf[(size_t)B_ * H_ * NBLK * VD_];
__device__ float g_pagg[(size_t)B_ * S_ * 256];

// ---------------- helpers ----------------
__device__ __forceinline__ float tf32r(float x) {
    unsigned r; asm("cvt.rna.tf32.f32 %0, %1;" : "=r"(r) : "f"(x));
    return __uint_as_float(r);
}
__device__ __forceinline__ unsigned u32f(float x) { return __float_as_uint(x); }

__device__ __forceinline__ void mma_tf32(float c[4],
    unsigned a0, unsigned a1, unsigned a2, unsigned a3,
    unsigned b0, unsigned b1)
{
    asm volatile(
        "mma.sync.aligned.m16n8k8.row.col.f32.tf32.tf32.f32 "
        "{%0,%1,%2,%3},{%4,%5,%6,%7},{%8,%9},{%0,%1,%2,%3};"
        : "+f"(c[0]), "+f"(c[1]), "+f"(c[2]), "+f"(c[3])
        : "r"(a0), "r"(a1), "r"(a2), "r"(a3), "r"(b0), "r"(b1));
}

__device__ __forceinline__ void cp16(float* dst, const float* src, bool valid) {
    unsigned d = (unsigned)__cvta_generic_to_shared(dst);
    int sz = valid ? 16 : 0;
    asm volatile("cp.async.ca.shared.global [%0], [%1], 16, %2;\n"
                 :: "r"(d), "l"(src), "r"(sz));
}
#define CP_COMMIT() asm volatile("cp.async.commit_group;\n" ::: "memory")
#define CP_WAIT1()  asm volatile("cp.async.wait_group 1;\n" ::: "memory")
#define CP_WAIT0()  asm volatile("cp.async.wait_group 0;\n" ::: "memory")

// 3-term split with explicit tf32 rounding of residuals (R6-R13 validated)
__device__ __forceinline__ void mma3(float acc[4],
    float q0, float q1, float q2, float q3, float b0v, float b1v)
{
    float h0 = tf32r(q0), h1 = tf32r(q1), h2 = tf32r(q2), h3 = tf32r(q3);
    float l0 = tf32r(q0 - h0), l1 = tf32r(q1 - h1);
    float l2 = tf32r(q2 - h2), l3 = tf32r(q3 - h3);
    float bh0 = tf32r(b0v), bh1 = tf32r(b1v);
    float bl0 = tf32r(b0v - bh0), bl1 = tf32r(b1v - bh1);
    mma_tf32(acc, u32f(h0), u32f(h1), u32f(h2), u32f(h3), u32f(bh0), u32f(bh1));
    mma_tf32(acc, u32f(l0), u32f(l1), u32f(l2), u32f(l3), u32f(bh0), u32f(bh1));
    mma_tf32(acc, u32f(h0), u32f(h1), u32f(h2), u32f(h3), u32f(bl0), u32f(bl1));
}

// ---------------- zero p_agg (float4, half per launch) ----------------
__global__ void zero_pagg_kernel(int half) {
    size_t n4 = (size_t)B_ * S_ * 256 / 4;
    size_t i = (size_t)half * (n4 / 2) + (size_t)blockIdx.x * blockDim.x + threadIdx.x;
    size_t end = (size_t)(half + 1) * (n4 / 2);
    if (i < end) ((float4*)g_pagg)[i] = make_float4(0.f, 0.f, 0.f, 0.f);
}

// ---------------- gathered split-K GEMM --------------------------------
// 128x64 block tile, 8x4 micro-tile, register-prefetch pipeline.
// Bit-identical per-output k-order to R13 (thread mapping change only).
#define AS2 132

__global__ void __launch_bounds__(256)
gather_gemm_kernel(const float* __restrict__ src,
                   const float* __restrict__ W,
                   int logF, int N, int KC, int mode)
{
    __shared__ float sA[16 * AS2];
    __shared__ float sB[16 * 64];
    float* scratch = mode ? g_scr_pe : g_scr_kv;
    const int F = 1 << logF;
    const int m0 = blockIdx.x * 128, n0 = blockIdx.y * 64;
    const int k0 = blockIdx.z * KC;
    const int t = threadIdx.x;
    const int ty = t >> 4, tx = t & 15;
    // loader maps
    const int ar0 = t >> 1, akq0 = (t & 1) * 8;    // unused alt; use idx form below
    (void)ar0; (void)akq0;

    float acc[8][4];
#pragma unroll
    for (int i = 0; i < 8; i++)
#pragma unroll
        for (int j = 0; j < 4; j++) acc[i][j] = 0.f;

    auto ldA = [&](int kt, int i) -> float4 {
        int idx = t + i * 256;
        int r = idx >> 2, kq = (idx & 3) * 4;
        int m = m0 + r;
        float4 v = make_float4(0.f, 0.f, 0.f, 0.f);
        if (m < 510) {
            int bb = (m >= NBLK) ? 1 : 0;
            int nb = m - bb * NBLK;
            int k = k0 + kt + kq;
            int p = k >> logF, c = k & (F - 1);
            v = *(const float4*)&src[(((size_t)bb * S_ + nb * STR_ + p) << logF) + c];
        }
        return v;
    };
    auto ldB = [&](int kt) -> float4 {
        int r = t >> 4, c4 = (t & 15) * 4;
        return *(const float4*)&W[(size_t)(k0 + kt + r) * N + n0 + c4];
    };

    float4 pa0 = ldA(0, 0), pa1 = ldA(0, 1), pb = ldB(0);

    const int nkt = KC / 16;
    for (int kt = 0; kt < nkt; kt++) {
        // store prefetched tile
        {
            int idx0 = t, idx1 = t + 256;
            int r0 = idx0 >> 2, kq0 = (idx0 & 3) * 4;
            sA[(kq0 + 0) * AS2 + r0] = pa0.x;
            sA[(kq0 + 1) * AS2 + r0] = pa0.y;
            sA[(kq0 + 2) * AS2 + r0] = pa0.z;
            sA[(kq0 + 3) * AS2 + r0] = pa0.w;
            int r1 = idx1 >> 2, kq1 = (idx1 & 3) * 4;
            sA[(kq1 + 0) * AS2 + r1] = pa1.x;
            sA[(kq1 + 1) * AS2 + r1] = pa1.y;
            sA[(kq1 + 2) * AS2 + r1] = pa1.z;
            sA[(kq1 + 3) * AS2 + r1] = pa1.w;
            *(float4*)&sB[(t >> 4) * 64 + (t & 15) * 4] = pb;
        }
        __syncthreads();
        if (kt + 1 < nkt) {
            pa0 = ldA((kt + 1) * 16, 0);
            pa1 = ldA((kt + 1) * 16, 1);
            pb  = ldB((kt + 1) * 16);
        }
#pragma unroll
        for (int kk = 0; kk < 16; kk++) {
            float4 a0 = *(const float4*)&sA[kk * AS2 + ty * 8];
            float4 a1 = *(const float4*)&sA[kk * AS2 + ty * 8 + 4];
            float4 bv = *(const float4*)&sB[kk * 64 + tx * 4];
            acc[0][0] += a0.x * bv.x; acc[0][1] += a0.x * bv.y; acc[0][2] += a0.x * bv.z; acc[0][3] += a0.x * bv.w;
            acc[1][0] += a0.y * bv.x; acc[1][1] += a0.y * bv.y; acc[1][2] += a0.y * bv.z; acc[1][3] += a0.y * bv.w;
            acc[2][0] += a0.z * bv.x; acc[2][1] += a0.z * bv.y; acc[2][2] += a0.z * bv.z; acc[2][3] += a0.z * bv.w;
            acc[3][0] += a0.w * bv.x; acc[3][1] += a0.w * bv.y; acc[3][2] += a0.w * bv.z; acc[3][3] += a0.w * bv.w;
            acc[4][0] += a1.x * bv.x; acc[4][1] += a1.x * bv.y; acc[4][2] += a1.x * bv.z; acc[4][3] += a1.x * bv.w;
            acc[5][0] += a1.y * bv.x; acc[5][1] += a1.y * bv.y; acc[5][2] += a1.y * bv.z; acc[5][3] += a1.y * bv.w;
            acc[6][0] += a1.z * bv.x; acc[6][1] += a1.z * bv.y; acc[6][2] += a1.z * bv.z; acc[6][3] += a1.z * bv.w;
            acc[7][0] += a1.w * bv.x; acc[7][1] += a1.w * bv.y; acc[7][2] += a1.w * bv.z; acc[7][3] += a1.w * bv.w;
        }
        __syncthreads();
    }
#pragma unroll
    for (int i = 0; i < 8; i++) {
        size_t row = (size_t)blockIdx.z * 512 + m0 + ty * 8 + i;
        *(float4*)&scratch[row * N + n0 + tx * 4] =
            make_float4(acc[i][0], acc[i][1], acc[i][2], acc[i][3]);
    }
}

// ---------------- split-K reduction ----------------
__global__ void reduce_kernel() {
    int i = blockIdx.x * blockDim.x + threadIdx.x;
    if (i < 510 * 512) {
        int m = i / 512, n = i % 512;
        float s = 0.f;
#pragma unroll
        for (int kc = 0; kc < KSPLIT; kc++) s += g_scr_kv[((size_t)kc * 512 + m) * 512 + n];
        g_cmp_kv[i] = s;
    } else if (i < 510 * 512 + 510 * 64) {
        int j = i - 510 * 512;
        int m = j / 64, e = j % 64;
        float s = 0.f;
#pragma unroll
        for (int kc = 0; kc < KSPLIT; kc++) s += g_scr_pe[((size_t)kc * 512 + m) * 64 + e];
        g_cmp_pe[j] = s;
    }
}

// ---------------- kvb GEMM (8x4, prefetch pipeline) + scatter -------------
__global__ void __launch_bounds__(256)
kvb_gemm_kernel(const float* __restrict__ Wkb)
{
    __shared__ float sA[16 * AS2];
    __shared__ float sB[16 * 64];
    const int m0 = blockIdx.x * 128, n0 = blockIdx.y * 64;
    const int t = threadIdx.x;
    const int ty = t >> 4, tx = t & 15;

    float acc[8][4];
#pragma unroll
    for (int i = 0; i < 8; i++)
#pragma unroll
        for (int j = 0; j < 4; j++) acc[i][j] = 0.f;

    auto ldA = [&](int kt, int i) -> float4 {
        int idx = t + i * 256;
        int r = idx >> 2, kq = (idx & 3) * 4;
        int m = m0 + r;
        float4 v = make_float4(0.f, 0.f, 0.f, 0.f);
        if (m < 510)
            v = *(const float4*)&g_cmp_kv[(size_t)m * 512 + kt + kq];
        return v;
    };
    auto ldB = [&](int kt) -> float4 {
        int r = t >> 4, c4 = (t & 15) * 4;
        return *(const float4*)&Wkb[(size_t)(kt + r) * 4096 + n0 + c4];
    };

    float4 pa0 = ldA(0, 0), pa1 = ldA(0, 1), pb = ldB(0);

    const int nkt = 512 / 16;
    for (int kt = 0; kt < nkt; kt++) {
        {
            int idx0 = t, idx1 = t + 256;
            int r0 = idx0 >> 2, kq0 = (idx0 & 3) * 4;
            sA[(kq0 + 0) * AS2 + r0] = pa0.x;
            sA[(kq0 + 1) * AS2 + r0] = pa0.y;
            sA[(kq0 + 2) * AS2 + r0] = pa0.z;
            sA[(kq0 + 3) * AS2 + r0] = pa0.w;
            int r1 = idx1 >> 2, kq1 = (idx1 & 3) * 4;
            sA[(kq1 + 0) * AS2 + r1] = pa1.x;
            sA[(kq1 + 1) * AS2 + r1] = pa1.y;
            sA[(kq1 + 2) * AS2 + r1] = pa1.z;
            sA[(kq1 + 3) * AS2 + r1] = pa1.w;
            *(float4*)&sB[(t >> 4) * 64 + (t & 15) * 4] = pb;
        }
        __syncthreads();
        if (kt + 1 < nkt) {
            pa0 = ldA((kt + 1) * 16, 0);
            pa1 = ldA((kt + 1) * 16, 1);
            pb  = ldB((kt + 1) * 16);
        }
#pragma unroll
        for (int kk = 0; kk < 16; kk++) {
            float4 a0 = *(const float4*)&sA[kk * AS2 + ty * 8];
            float4 a1 = *(const float4*)&sA[kk * AS2 + ty * 8 + 4];
            float4 bv = *(const float4*)&sB[kk * 64 + tx * 4];
            acc[0][0] += a0.x * bv.x; acc[0][1] += a0.x * bv.y; acc[0][2] += a0.x * bv.z; acc[0][3] += a0.x * bv.w;
            acc[1][0] += a0.y * bv.x; acc[1][1] += a0.y * bv.y; acc[1][2] += a0.y * bv.z; acc[1][3] += a0.y * bv.w;
            acc[2][0] += a0.z * bv.x; acc[2][1] += a0.z * bv.y; acc[2][2] += a0.z * bv.z; acc[2][3] += a0.z * bv.w;
            acc[3][0] += a0.w * bv.x; acc[3][1] += a0.w * bv.y; acc[3][2] += a0.w * bv.z; acc[3][3] += a0.w * bv.w;
            acc[4][0] += a1.x * bv.x; acc[4][1] += a1.x * bv.y; acc[4][2] += a1.x * bv.z; acc[4][3] += a1.x * bv.w;
            acc[5][0] += a1.y * bv.x; acc[5][1] += a1.y * bv.y; acc[5][2] += a1.y * bv.z; acc[5][3] += a1.y * bv.w;
            acc[6][0] += a1.z * bv.x; acc[6][1] += a1.z * bv.y; acc[6][2] += a1.z * bv.z; acc[6][3] += a1.z * bv.w;
            acc[7][0] += a1.w * bv.x; acc[7][1] += a1.w * bv.y; acc[7][2] += a1.w * bv.z; acc[7][3] += a1.w * bv.w;
        }
        __syncthreads();
    }
    // scatter: a 4-aligned col quad never straddles d=128 (K/V split)
#pragma unroll
    for (int i = 0; i < 8; i++) {
        int m = m0 + ty * 8 + i;
        if (m >= 510) continue;
        int bb = (m >= NBLK) ? 1 : 0;
        int nb = m - bb * NBLK;
        int col = n0 + tx * 4;
        int hh = col >> 8, d = col & 255;
        float4 v = make_float4(acc[i][0], acc[i][1], acc[i][2], acc[i][3]);
        if (d < 128)
            *(float4*)&g_Kf[((size_t)((bb * H_ + hh) * NBLK + nb)) * QKD_ + d] = v;
        else
            *(float4*)&g_Vf[((size_t)((bb * H_ + hh) * NBLK + nb)) * VD_ + (d - 128)] = v;
    }
}

// ---------------- broadcast rope into Kf[...,128:192] ----------------
__global__ void rope_fill_kernel() {
    int i = blockIdx.x * blockDim.x + threadIdx.x;
    const int tot = B_ * H_ * NBLK * ROPE_;
    if (i >= tot) return;
    int e = i & 63;
    int nb = (i >> 6) % NBLK;
    int h = (i / (64 * NBLK)) % H_;
    int b = i / (64 * NBLK * H_);
    g_Kf[((size_t)((b * H_ + h) * NBLK + nb)) * QKD_ + 128 + e] = g_cmp_pe[((size_t)(b * NBLK + nb)) * 64 + e];
}

// ---------------- attention (exact R11/R13 version) ----------------
#define SP  260
#define QS  196
#define KS2 196
#define VS2 136
#define ATTN_SMEM_FLOATS (32 * SP + 19200)

__global__ void __launch_bounds__(256, 2)
attn_kernel(const float* __restrict__ q, float* __restrict__ out)
{
    extern __shared__ float sm[];
    float* sS   = sm;
    float* sBuf = sm + 32 * SP;
    float* sQ   = sBuf;
    float* sK0  = sBuf + 6400;
    float* sK1  = sBuf + 12672;
    float* sV0  = sBuf;
    float* sV1  = sBuf + 8704;

    const int qt = (int)gridDim.x - 1 - (int)blockIdx.x;
    const int h = blockIdx.y, b = blockIdx.z;
    const int s0 = qt * 32;
    const int t = threadIdx.x;
    const int w = t >> 5, lane = t & 31;
    const int g = lane >> 2, tig = lane & 3;
    const int mrow = 16 * (w & 1);
    const int nloc8 = (w >> 1) * 8;

    const int nmax_tile = s0 >> 4;
    const int nkt = min(8, nmax_tile / 32 + 1);
    const int nvt = min(4, nmax_tile / 64 + 1);
    const int ncols = nvt * 64;

    const float* Kb = g_Kf + (size_t)(b * H_ + h) * NBLK * QKD_;
    const float* Vb = g_Vf + (size_t)(b * H_ + h) * NBLK * VD_;

    for (int i = t; i < 32 * 48; i += 256) {
        int r = i / 48, c = i % 48;
        cp16(sK0 + r * KS2 + c * 4, Kb + (size_t)r * QKD_ + c * 4, r < NBLK);
    }
    CP_COMMIT();

    const float* qb = q + ((size_t)(b * S_ + s0) * H_ + h) * QKD_;
    for (int i = t; i < 32 * 48; i += 256) {
        int r = i / 48, c = i % 48;
        float4 v = ((const float4*)(qb + (size_t)r * H_ * QKD_))[c];
        *(float4*)(sQ + r * QS + c * 4) = v;
    }

    for (int nt = 0; nt < nkt; nt++) {
        if (nt + 1 < nkt) {
            float* dst = ((nt + 1) & 1) ? sK1 : sK0;
            int n0 = (nt + 1) * 32;
            for (int i = t; i < 32 * 48; i += 256) {
                int r = i / 48, c = i % 48;
                int n = n0 + r;
                cp16(dst + r * KS2 + c * 4, Kb + (size_t)n * QKD_ + c * 4, n < NBLK);
            }
            CP_COMMIT();
            CP_WAIT1();
        } else {
            CP_WAIT0();
        }
        __syncthreads();

        const float* sK = (nt & 1) ? sK1 : sK0;
        float acc[4] = {0.f, 0.f, 0.f, 0.f};
#pragma unroll 2
        for (int k0 = 0; k0 < 192; k0 += 8) {
            float q0 = sQ[(mrow + g) * QS + k0 + tig];
            float q1 = sQ[(mrow + g + 8) * QS + k0 + tig];
            float q2 = sQ[(mrow + g) * QS + k0 + tig + 4];
            float q3 = sQ[(mrow + g + 8) * QS + k0 + tig + 4];
            float kv0 = sK[(nloc8 + g) * KS2 + k0 + tig];
            float kv1 = sK[(nloc8 + g) * KS2 + k0 + tig + 4];
            mma3(acc, q0, q1, q2, q3, kv0, kv1);
        }
        int col = nt * 32 + nloc8 + 2 * tig;
        *(float2*)(sS + (mrow + g) * SP + col)     = make_float2(acc[0], acc[1]);
        *(float2*)(sS + (mrow + g + 8) * SP + col) = make_float2(acc[2], acc[3]);
        __syncthreads();
    }

    for (int i = t; i < 64 * 32; i += 256) {
        int r = i / 32, c = i % 32;
        cp16(sV0 + r * VS2 + c * 4, Vb + (size_t)r * VD_ + c * 4, r < NBLK);
    }
    CP_COMMIT();

    const int tx = lane;
    for (int rr = 0; rr < 4; rr++) {
        int r = w * 4 + rr;
        int s = s0 + r;
        int nmax = (s >= 31) ? ((s - 31) >> 4) : -1;
        float m = -3.4e38f;
        for (int n = tx; n <= nmax; n += 32)
            m = fmaxf(m, sS[r * SP + n] * SCALE_);
#pragma unroll
        for (int o = 16; o; o >>= 1) m = fmaxf(m, __shfl_xor_sync(0xffffffffu, m, o));
        float L = 0.f;
        for (int n = tx; n < ncols; n += 32) {
            float e = 0.f;
            if (n <= nmax) e = __expf(sS[r * SP + n] * SCALE_ - m);
            sS[r * SP + n] = e;
            L += e;
        }
#pragma unroll
        for (int o = 16; o; o >>= 1) L += __shfl_xor_sync(0xffffffffu, L, o);
        if (nmax >= 0) {
            float inv = 1.f / L;
            for (int n = tx; n <= nmax; n += 32) {
                float p = sS[r * SP + n] * inv;
                sS[r * SP + n] = p;
                atomicMax((int*)&g_pagg[(size_t)(b * S_ + s) * 256 + n], __float_as_int(p));
            }
        }
    }
    __syncthreads();

    const int nquad = w >> 1;
    float oa[4][4];
#pragma unroll
    for (int j = 0; j < 4; j++)
#pragma unroll
        for (int e = 0; e < 4; e++) oa[j][e] = 0.f;

    for (int vt = 0; vt < nvt; vt++) {
        if (vt + 1 < nvt) {
            float* dst = ((vt + 1) & 1) ? sV1 : sV0;
            int n0 = (vt + 1) * 64;
            for (int i = t; i < 64 * 32; i += 256) {
                int r = i / 32, c = i % 32;
                int n = n0 + r;
                cp16(dst + r * VS2 + c * 4, Vb + (size_t)n * VD_ + c * 4, n < NBLK);
            }
            CP_COMMIT();
            CP_WAIT1();
        } else {
            CP_WAIT0();
        }
        __syncthreads();

        const float* sV = (vt & 1) ? sV1 : sV0;
#pragma unroll 2
        for (int ks = 0; ks < 64; ks += 8) {
            int k0 = vt * 64 + ks;
            unsigned a0 = u32f(tf32r(sS[(mrow + g) * SP + k0 + tig]));
            unsigned a1 = u32f(tf32r(sS[(mrow + g + 8) * SP + k0 + tig]));
            unsigned a2 = u32f(tf32r(sS[(mrow + g) * SP + k0 + tig + 4]));
            unsigned a3 = u32f(tf32r(sS[(mrow + g + 8) * SP + k0 + tig + 4]));
#pragma unroll
            for (int j = 0; j < 4; j++) {
                const float* vb = sV + (ks + tig) * VS2 + nquad * 32 + j * 8 + g;
                unsigned b0 = u32f(tf32r(vb[0]));
                unsigned b1 = u32f(tf32r(vb[4 * VS2]));
                mma_tf32(oa[j], a0, a1, a2, a3, b0, b1);
            }
        }
        __syncthreads();
    }

#pragma unroll
    for (int j = 0; j < 4; j++) {
        int col = nquad * 32 + j * 8 + 2 * tig;
        {
            int s = s0 + mrow + g;
            float* orow = out + (size_t)(b * S_ + s) * (H_ * VD_) + h * VD_ + col;
            *(float2*)orow = make_float2(oa[j][0], oa[j][1]);
        }
        {
            int s = s0 + mrow + g + 8;
            float* orow = out + (size_t)(b * S_ + s) * (H_ * VD_) + h * VD_ + col;
            *(float2*)orow = make_float2(oa[j][2], oa[j][3]);
        }
    }
}

// ---------------- top-k selection ----------------
__global__ void topk_kernel(float* __restrict__ out)
{
    int idx = blockIdx.x * blockDim.x + threadIdx.x;
    if (idx >= B_ * S_) return;
    int s = idx & (S_ - 1);
    int jt = s >> 6;
    const float* pa = g_pagg + (size_t)idx * 256;

    float sc[64];
#pragma unroll 1
    for (int j = 0; j < 64; j++) {
        if (j > jt)                { sc[j] = -1e9f; continue; }
        if (j == 0 || j >= jt - 1) { sc[j] =  1e9f; continue; }
        int nlo = 4 * j - 1;
        int nhi = min(NBLK - 1, 4 * j + 3);
        float sum = 0.f;
        for (int n = nlo; n <= nhi; n++) sum += pa[n];
        sc[j] = sum;
    }
    float* o = out + (size_t)B_ * S_ * (H_ * VD_) + (size_t)idx * TOPK_;
#pragma unroll 1
    for (int k = 0; k < TOPK_; k++) {
        float best = -3.4e38f; int bi = 0;
        for (int j = 0; j < 64; j++)
            if (sc[j] > best) { best = sc[j]; bi = j; }
        o[k] = (best <= -5e8f) ? -1.f : (float)bi;
        sc[bi] = -3.4e38f;
    }
}

// ---------------- launch ----------------
extern "C" void kernel_launch(void* const* d_in, const int* in_sizes, int n_in,
                              void* d_out, int out_size)
{
    const float* q       = (const float*)d_in[0];
    const float* kv_lora = (const float*)d_in[1];
    const float* k_pe    = (const float*)d_in[2];
    const float* Wck     = (const float*)d_in[3];
    const float* Wcp     = (const float*)d_in[4];
    const float* Wkb     = (const float*)d_in[5];
    float* out = (float*)d_out;

    cudaFuncSetAttribute(attn_kernel, cudaFuncAttributeMaxDynamicSharedMemorySize,
                         ATTN_SMEM_FLOATS * (int)sizeof(float));

    const unsigned zblk = (unsigned)(((size_t)B_ * S_ * 256 / 8) + 255) / 256;

    // 0) zero p_agg (first half)
    zero_pagg_kernel<<<zblk, 256>>>(0);
    // 1) cmp_pe split-K: M=512(510), N=64, K=2048
    gather_gemm_kernel<<<dim3(4, 1, KSPLIT), 256>>>(k_pe, Wcp, 6, 64, 256, 1);
    // 2) zero p_agg (second half)
    zero_pagg_kernel<<<zblk, 256>>>(1);
    // 3) cmp_kv split-K  (ncu capture slot)
    gather_gemm_kernel<<<dim3(4, 8, KSPLIT), 256>>>(kv_lora, Wck, 9, 512, 2048, 0);
    // 4) reduce partials
    {
        int tot = 510 * 512 + 510 * 64;
        reduce_kernel<<<(tot + 255) / 256, 256>>>();
    }
    // 5) kvb GEMM + scatter to Kf/Vf
    kvb_gemm_kernel<<<dim3(4, 64), 256>>>(Wkb);
    // 6) rope broadcast into Kf
    {
        int tot = B_ * H_ * NBLK * ROPE_;
        rope_fill_kernel<<<(tot + 255) / 256, 256>>>();
    }
    // 7) attention (+ probs max into p_agg)
    attn_kernel<<<dim3(S_ / 32, H_, B_), 256, ATTN_SMEM_FLOATS * (int)sizeof(float)>>>(q, out);
    // 8) top-k indices
    topk_kernel<<<(B_ * S_ + 255) / 256, 256>>>(out);
}